// round 8
// baseline (speedup 1.0000x reference)
#include <cuda_runtime.h>
#include <cuda_bf16.h>
#include <math.h>
#include <stdint.h>

#define S_  2048
#define E_  2048
#define H_  16
#define QR_ 512
#define KVR_ 512
#define DR_ 64
#define DV_ 128
#define DQK_ 192   // DV + DR
#define NDWN 1088  // QR + KVR + DR
#define NQU  3072  // H*DV + H*DR

typedef __nv_bfloat16 bf16;

// ---------------- scratch (device globals) ----------------
// planar tf32 hi/lo splits
__device__ float g_xh [S_*E_],        g_xl [S_*E_];
__device__ float g_wdh[NDWN*E_],      g_wdl[NDWN*E_];      // concat [wq_down; wkv_down; wk_rope]
__device__ float g_wuh[NQU*QR_],      g_wul[NQU*QR_];      // concat [wq_up; wq_rope]
__device__ float g_wkvuh[H_*2*DV_*KVR_], g_wkvul[H_*2*DV_*KVR_];
__device__ float g_down [S_*NDWN];                          // fp32 [cq|ckv|kr]
__device__ float g_dwnh[S_*NDWN],     g_dwnl[S_*NDWN];
__device__ float g_qu [S_*NQU];
__device__ float g_kv [S_*(H_*2*DV_)];
__device__ bf16 g_wo_h[E_*H_*DV_], g_wo_l[E_*H_*DV_];
__device__ bf16 g_q[(size_t)H_ * S_ * DQK_];
__device__ bf16 g_k[(size_t)H_ * S_ * DQK_];
__device__ bf16 g_v[(size_t)H_ * S_ * DV_];
__device__ bf16 g_vT[(size_t)H_ * DV_ * S_];
__device__ bf16 g_logits[(size_t)H_ * S_ * S_];
__device__ bf16 g_probs [(size_t)H_ * S_ * S_];
__device__ bf16 g_attn_bf[(size_t)S_ * H_ * DV_];

// ---------------- helpers ----------------
__device__ __forceinline__ uint32_t f2tf32(float x) {
    uint32_t r;
    asm("cvt.rna.tf32.f32 %0, %1;" : "=r"(r) : "f"(x));
    return r;
}

#define MMA_TF32(c, a, b) \
    asm volatile( \
        "mma.sync.aligned.m16n8k8.row.col.f32.tf32.tf32.f32 " \
        "{%0,%1,%2,%3}, {%4,%5,%6,%7}, {%8,%9}, {%0,%1,%2,%3};" \
        : "+f"((c)[0]), "+f"((c)[1]), "+f"((c)[2]), "+f"((c)[3]) \
        : "r"((a)[0]), "r"((a)[1]), "r"((a)[2]), "r"((a)[3]), \
          "r"((b)[0]), "r"((b)[1]))

#define MMA_BF16(c, a, b) \
    asm volatile( \
        "mma.sync.aligned.m16n8k16.row.col.f32.bf16.bf16.f32 " \
        "{%0,%1,%2,%3}, {%4,%5,%6,%7}, {%8,%9}, {%0,%1,%2,%3};" \
        : "+f"((c)[0]), "+f"((c)[1]), "+f"((c)[2]), "+f"((c)[3]) \
        : "r"((a)[0]), "r"((a)[1]), "r"((a)[2]), "r"((a)[3]), \
          "r"((b)[0]), "r"((b)[1]))

#define CP16(dst, src, nbytes) \
    asm volatile("cp.async.cg.shared.global [%0], [%1], 16, %2;" \
                 :: "r"(dst), "l"(src), "r"(nbytes))
#define CP_COMMIT()  asm volatile("cp.async.commit_group;")
#define CP_WAIT0()   asm volatile("cp.async.wait_group 0;")

// ---------------- split kernels ----------------
__global__ void split_tf32_pl(const float* __restrict__ src, float* __restrict__ hi,
                              float* __restrict__ lo, long n)
{
    long i = (long)blockIdx.x * blockDim.x + threadIdx.x;
    long stride = (long)gridDim.x * blockDim.x;
    for (; i < n; i += stride) {
        float v = src[i];
        uint32_t h = f2tf32(v);
        hi[i] = __uint_as_float(h);
        lo[i] = __uint_as_float(f2tf32(v - __uint_as_float(h)));
    }
}

__global__ void split_bf_k(const float* __restrict__ src, bf16* __restrict__ hi,
                           bf16* __restrict__ lo, long n)
{
    long i = (long)blockIdx.x * blockDim.x + threadIdx.x;
    long stride = (long)gridDim.x * blockDim.x;
    for (; i < n; i += stride) {
        float v = src[i];
        bf16 h = __float2bfloat16(v);
        hi[i] = h;
        lo[i] = __float2bfloat16(v - __bfloat162float(h));
    }
}

// ============================================================================
// 3xTF32 GEMM on planar pre-split hi/lo operands (4 planes in smem, each with
// the proven conflict-free FPAD layout). Zero CVT/FSUB in the inner loop.
// Chunked-IEEE accumulation (6-mma chain from zero fragment, then IEEE FADD).
// cp.async double-buffered. Dynamic smem = 80 KB.
// ============================================================================
#define FBM 128
#define FBN 128
#define FBK 16
#define FPAD 20
#define PSF (FBM * FPAD)          // floats per plane
#define PBB (PSF * 4u)            // bytes per plane

__global__ __launch_bounds__(256)
void tf32_gemm(const float* __restrict__ Ah, const float* __restrict__ Al,
               const float* __restrict__ Bh, const float* __restrict__ Bl,
               float* __restrict__ C, int M, int N, int K,
               long lda, long ldb, long ldc)
{
    extern __shared__ float dsm[];   // [2 bufs][4 planes][PSF]

    const int m0 = blockIdx.y * FBM;
    const int n0 = blockIdx.x * FBN;
    const int tid = threadIdx.x;
    const int warp = tid >> 5;
    const int lane = tid & 31;
    const int gid = lane >> 2;
    const int tig = lane & 3;
    const int wm = (warp >> 1) * 32;
    const int wn = (warp & 1) * 64;

    const float *ahS[2], *alS[2], *bhS[2], *blS[2];
    uint32_t sOff[2];
    int bPred[2];
    const uint32_t base = (uint32_t)__cvta_generic_to_shared(dsm);
#pragma unroll
    for (int it = 0; it < 2; it++) {
        int idx = tid + it * 256;
        int row = idx >> 2, ch = idx & 3;
        long ao = (long)(m0 + row) * lda + ch * 4;
        ahS[it] = Ah + ao;  alS[it] = Al + ao;
        int nrow = n0 + row;
        bPred[it] = (nrow < N) ? 16 : 0;
        if (nrow >= N) nrow = N - 1;
        long bo = (long)nrow * ldb + ch * 4;
        bhS[it] = Bh + bo;  blS[it] = Bl + bo;
        sOff[it] = (uint32_t)(row * FPAD + ch * 4) * 4u;
    }
    const uint32_t BUFB = 4u * PBB;   // bytes per buffer (4 planes)

    float acc[2][8][4];
#pragma unroll
    for (int mt = 0; mt < 2; mt++)
#pragma unroll
        for (int nt = 0; nt < 8; nt++)
#pragma unroll
            for (int r = 0; r < 4; r++) acc[mt][nt][r] = 0.f;

    const int NT = K / FBK;

    // prologue: tile 0 -> buf 0
#pragma unroll
    for (int it = 0; it < 2; it++) {
        CP16(base + 0*PBB + sOff[it], ahS[it], 16);
        CP16(base + 1*PBB + sOff[it], alS[it], 16);
        CP16(base + 2*PBB + sOff[it], bhS[it], bPred[it]);
        CP16(base + 3*PBB + sOff[it], blS[it], bPred[it]);
    }
    CP_COMMIT();

    for (int t = 0; t < NT; t++) {
        const int cur = t & 1;
        CP_WAIT0();
        __syncthreads();

        if (t + 1 < NT) {
            const long kk = (long)(t + 1) * FBK;
            const uint32_t bb = base + (cur ^ 1) * BUFB;
#pragma unroll
            for (int it = 0; it < 2; it++) {
                CP16(bb + 0*PBB + sOff[it], ahS[it] + kk, 16);
                CP16(bb + 1*PBB + sOff[it], alS[it] + kk, 16);
                CP16(bb + 2*PBB + sOff[it], bhS[it] + kk, bPred[it]);
                CP16(bb + 3*PBB + sOff[it], blS[it] + kk, bPred[it]);
            }
            CP_COMMIT();
        }

        const float* cAh = dsm + (cur * 4 + 0) * PSF;
        const float* cAl = dsm + (cur * 4 + 1) * PSF;
        const float* cBh = dsm + (cur * 4 + 2) * PSF;
        const float* cBl = dsm + (cur * 4 + 3) * PSF;

        uint32_t ah[2][2][4], al[2][2][4];
#pragma unroll
        for (int ks = 0; ks < 2; ks++)
#pragma unroll
            for (int mt = 0; mt < 2; mt++)
#pragma unroll
                for (int r = 0; r < 4; r++) {
                    int off = (wm + mt * 16 + gid + (r & 1) * 8) * FPAD
                            + ks * 8 + tig + (r >> 1) * 4;
                    ah[ks][mt][r] = __float_as_uint(cAh[off]);
                    al[ks][mt][r] = __float_as_uint(cAl[off]);
                }

#pragma unroll
        for (int nt = 0; nt < 8; nt++) {
            uint32_t bh[2][2], bl[2][2];
#pragma unroll
            for (int ks = 0; ks < 2; ks++)
#pragma unroll
                for (int r = 0; r < 2; r++) {
                    int off = (wn + nt * 8 + gid) * FPAD + ks * 8 + tig + r * 4;
                    bh[ks][r] = __float_as_uint(cBh[off]);
                    bl[ks][r] = __float_as_uint(cBl[off]);
                }
#pragma unroll
            for (int mt = 0; mt < 2; mt++) {
                float f[4] = {0.f, 0.f, 0.f, 0.f};
#pragma unroll
                for (int ks = 0; ks < 2; ks++) {
                    MMA_TF32(f, ah[ks][mt], bh[ks]);
                    MMA_TF32(f, ah[ks][mt], bl[ks]);
                    MMA_TF32(f, al[ks][mt], bh[ks]);
                }
                float* c = acc[mt][nt];
                c[0] += f[0]; c[1] += f[1]; c[2] += f[2]; c[3] += f[3];
            }
        }
    }

#pragma unroll
    for (int mt = 0; mt < 2; mt++) {
        int row0 = m0 + wm + mt * 16 + gid;
#pragma unroll
        for (int nt = 0; nt < 8; nt++) {
            int n = n0 + wn + nt * 8 + tig * 2;
            if (n >= N) continue;
            float* c = acc[mt][nt];
            C[(long)row0 * ldc + n]         = c[0];
            C[(long)row0 * ldc + n + 1]     = c[1];
            C[(long)(row0+8) * ldc + n]     = c[2];
            C[(long)(row0+8) * ldc + n + 1] = c[3];
        }
    }
}

// ============================================================================
// bf16 tensor-core GEMM, chunked-IEEE accumulation, cp.async double-buffered,
// multi-pass (npass operand pairs accumulated in fp32). (unchanged from R7)
// ============================================================================
#define TBM 128
#define TBN 128
#define TBK 32
#define PADK 40

template <typename TC>
__global__ __launch_bounds__(256)
void bf16_gemm(const bf16* __restrict__ A0, const bf16* __restrict__ A1,
               const bf16* __restrict__ B0, const bf16* __restrict__ B1,
               TC* __restrict__ C, int npass, int M, int N, int K,
               long lda, long ldb, long ldc, long Abat, long Bbat, long Cbat)
{
    __shared__ bf16 sA[2][TBM * PADK];
    __shared__ bf16 sB[2][TBN * PADK];

    const long zo = blockIdx.z;
    C += zo * Cbat;

    const int m0 = blockIdx.y * TBM;
    const int n0 = blockIdx.x * TBN;
    const int tid = threadIdx.x;
    const int warp = tid >> 5;
    const int lane = tid & 31;
    const int gid = lane >> 2;
    const int tig = lane & 3;
    const int wm = (warp >> 1) * 32;
    const int wn = (warp & 1) * 64;

    const uint32_t saBase = (uint32_t)__cvta_generic_to_shared(sA);
    const uint32_t sbBase = (uint32_t)__cvta_generic_to_shared(sB);
    const uint32_t ABUF = TBM * PADK * 2u;

    float acc[2][8][4];
#pragma unroll
    for (int mt = 0; mt < 2; mt++)
#pragma unroll
        for (int nt = 0; nt < 8; nt++)
#pragma unroll
            for (int r = 0; r < 4; r++) acc[mt][nt][r] = 0.f;

    const int NT = K / TBK;

    for (int p = 0; p < npass; p++) {
        const bf16* A = (p ? A1 : A0) + zo * Abat;
        const bf16* B = (p ? B1 : B0) + zo * Bbat;

        const bf16* aSrc[2];
        const bf16* bSrc[2];
        uint32_t sOff[2];
        int bPred[2];
#pragma unroll
        for (int it = 0; it < 2; it++) {
            int idx = tid + it * 256;
            int row = idx >> 2, ch = idx & 3;
            aSrc[it] = A + (long)(m0 + row) * lda + ch * 8;
            int nrow = n0 + row;
            bPred[it] = (nrow < N) ? 16 : 0;
            if (nrow >= N) nrow = N - 1;
            bSrc[it] = B + (long)nrow * ldb + ch * 8;
            sOff[it] = (uint32_t)(row * PADK + ch * 8) * 2u;
        }

        if (p) __syncthreads();

#pragma unroll
        for (int it = 0; it < 2; it++) {
            CP16(saBase + sOff[it], aSrc[it], 16);
            CP16(sbBase + sOff[it], bSrc[it], bPred[it]);
        }
        CP_COMMIT();

        for (int t = 0; t < NT; t++) {
            const int cur = t & 1;
            CP_WAIT0();
            __syncthreads();

            if (t + 1 < NT) {
                const long kk = (long)(t + 1) * TBK;
                const uint32_t bo = (cur ^ 1) * ABUF;
#pragma unroll
                for (int it = 0; it < 2; it++) {
                    CP16(saBase + bo + sOff[it], aSrc[it] + kk, 16);
                    CP16(sbBase + bo + sOff[it], bSrc[it] + kk, bPred[it]);
                }
                CP_COMMIT();
            }

            const bf16* cA = sA[cur];
            const bf16* cB = sB[cur];

            uint32_t a[2][2][4];
#pragma unroll
            for (int ks = 0; ks < 2; ks++)
#pragma unroll
                for (int mt = 0; mt < 2; mt++)
#pragma unroll
                    for (int r = 0; r < 4; r++) {
                        int row = wm + mt * 16 + gid + (r & 1) * 8;
                        int col = ks * 16 + tig * 2 + (r >> 1) * 8;
                        a[ks][mt][r] = *(const uint32_t*)&cA[row * PADK + col];
                    }

#pragma unroll
            for (int nt = 0; nt < 8; nt++) {
                uint32_t b[2][2];
#pragma unroll
                for (int ks = 0; ks < 2; ks++)
#pragma unroll
                    for (int r = 0; r < 2; r++) {
                        int n  = wn + nt * 8 + gid;
                        int kq = ks * 16 + tig * 2 + r * 8;
                        b[ks][r] = *(const uint32_t*)&cB[n * PADK + kq];
                    }
#pragma unroll
                for (int mt = 0; mt < 2; mt++) {
                    float f[4] = {0.f, 0.f, 0.f, 0.f};
                    MMA_BF16(f, a[0][mt], b[0]);
                    MMA_BF16(f, a[1][mt], b[1]);
                    float* c = acc[mt][nt];
                    c[0] += f[0]; c[1] += f[1]; c[2] += f[2]; c[3] += f[3];
                }
            }
        }
    }

#pragma unroll
    for (int mt = 0; mt < 2; mt++) {
        int row0 = m0 + wm + mt * 16 + gid;
#pragma unroll
        for (int nt = 0; nt < 8; nt++) {
            int n = n0 + wn + nt * 8 + tig * 2;
            if (n >= N) continue;
            float* c = acc[mt][nt];
            if (sizeof(TC) == 4) {
                float* Cf = (float*)C;
                Cf[(long)row0 * ldc + n]         = c[0];
                Cf[(long)row0 * ldc + n + 1]     = c[1];
                Cf[(long)(row0+8) * ldc + n]     = c[2];
                Cf[(long)(row0+8) * ldc + n + 1] = c[3];
            } else {
                bf16* Cb = (bf16*)C;
                *(__nv_bfloat162*)&Cb[(long)row0 * ldc + n] =
                    __nv_bfloat162(__float2bfloat16(c[0]), __float2bfloat16(c[1]));
                *(__nv_bfloat162*)&Cb[(long)(row0+8) * ldc + n] =
                    __nv_bfloat162(__float2bfloat16(c[2]), __float2bfloat16(c[3]));
            }
        }
    }
}

// ---------------- pack q/k/v (bf16, head-major) + RoPE ----------------
__global__ void pack_k(const float* __restrict__ qu, const float* __restrict__ kvf,
                       const float* __restrict__ dwn,
                       bf16* __restrict__ q, bf16* __restrict__ k, bf16* __restrict__ v)
{
    const int s = blockIdx.x;
    const int tid = threadIdx.x;  // 256

    __shared__ float ssin[32], scos[32];
    if (tid < 32) {
        double invf_d = pow(10000.0, -((double)(2 * tid)) / 64.0);
        float invf = (float)invf_d;
        float ang = (float)s * invf;
        double a = (double)ang;
        ssin[tid] = (float)sin(a);
        scos[tid] = (float)cos(a);
    }
    __syncthreads();

    for (int idx = tid; idx < H_ * DV_; idx += 256) {
        int h = idx >> 7, d = idx & 127;
        q[((long)h * S_ + s) * DQK_ + d] = __float2bfloat16(qu[(long)s * NQU + idx]);
        k[((long)h * S_ + s) * DQK_ + d] = __float2bfloat16(kvf[(long)s * (H_*2*DV_) + idx]);
        v[((long)h * S_ + s) * DV_ + d]  = __float2bfloat16(kvf[(long)s * (H_*2*DV_) + H_*DV_ + idx]);
    }

    for (int idx = tid; idx < H_ * 32; idx += 256) {
        int h = idx >> 5, j = idx & 31;
        float x1 = qu[(long)s * NQU + 2048 + h * DR_ + j];
        float x2 = qu[(long)s * NQU + 2048 + h * DR_ + 32 + j];
        float sn = ssin[j], cs = scos[j];
        q[((long)h * S_ + s) * DQK_ + DV_ + j]      = __float2bfloat16(x1 * cs - x2 * sn);
        q[((long)h * S_ + s) * DQK_ + DV_ + 32 + j] = __float2bfloat16(x2 * cs + x1 * sn);
    }

    if (tid < 32) {
        int j = tid;
        float x1 = dwn[(long)s * NDWN + 1024 + j];
        float x2 = dwn[(long)s * NDWN + 1024 + 32 + j];
        float sn = ssin[j], cs = scos[j];
        float r1 = x1 * cs - x2 * sn;
        float r2 = x2 * cs + x1 * sn;
#pragma unroll
        for (int h = 0; h < H_; h++) {
            k[((long)h * S_ + s) * DQK_ + DV_ + j]      = __float2bfloat16(r1);
            k[((long)h * S_ + s) * DQK_ + DV_ + 32 + j] = __float2bfloat16(r2);
        }
    }
}

// ---------------- transpose v [h][s][d] -> vT [h][d][s] ----------------
__global__ void transpose_v(const bf16* __restrict__ v, bf16* __restrict__ vT)
{
    __shared__ bf16 t[32][33];
    const int h = blockIdx.z;
    const int s0 = blockIdx.x * 32;
    const int d0 = blockIdx.y * 32;
    const int tx = threadIdx.x, ty = threadIdx.y;  // (32, 8)
#pragma unroll
    for (int j = 0; j < 32; j += 8)
        t[ty + j][tx] = v[((long)h * S_ + s0 + ty + j) * DV_ + d0 + tx];
    __syncthreads();
#pragma unroll
    for (int j = 0; j < 32; j += 8)
        vT[((long)h * DV_ + d0 + ty + j) * S_ + s0 + tx] = t[tx][ty + j];
}

// ---------------- softmax over bf16 logits -> bf16 probs ----------------
__global__ void softmax_k(const bf16* __restrict__ L, bf16* __restrict__ P, float scale)
{
    const int s = blockIdx.x;
    const int h = blockIdx.y;
    const bf16* row = L + ((long)h * S_ + s) * S_;
    bf16* prow = P + ((long)h * S_ + s) * S_;
    const int tid = threadIdx.x;

    float v[8];
    float mx = -1e30f;
#pragma unroll
    for (int i = 0; i < 8; i++) {
        v[i] = __bfloat162float(row[tid + i * 256]) * scale;
        mx = fmaxf(mx, v[i]);
    }
    __shared__ float red[256];
    red[tid] = mx;
    __syncthreads();
    for (int st = 128; st > 0; st >>= 1) {
        if (tid < st) red[tid] = fmaxf(red[tid], red[tid + st]);
        __syncthreads();
    }
    mx = red[0];
    __syncthreads();

    float sum = 0.f;
#pragma unroll
    for (int i = 0; i < 8; i++) {
        v[i] = expf(v[i] - mx);
        sum += v[i];
    }
    red[tid] = sum;
    __syncthreads();
    for (int st = 128; st > 0; st >>= 1) {
        if (tid < st) red[tid] += red[tid + st];
        __syncthreads();
    }
    float tot = red[0];
#pragma unroll
    for (int i = 0; i < 8; i++)
        prow[tid + i * 256] = __float2bfloat16(v[i] / tot);
}

// ---------------- orchestration ----------------
extern "C" void kernel_launch(void* const* d_in, const int* in_sizes, int n_in,
                              void* d_out, int out_size)
{
    (void)in_sizes; (void)n_in; (void)out_size;
    const float* x       = (const float*)d_in[0];
    const float* wq_down = (const float*)d_in[1];
    const float* wq_up   = (const float*)d_in[2];
    const float* wq_rope = (const float*)d_in[3];
    const float* wkv_down= (const float*)d_in[4];
    const float* wkv_up  = (const float*)d_in[5];
    const float* wk_rope = (const float*)d_in[6];
    const float* wo      = (const float*)d_in[7];
    float* out = (float*)d_out;

    float *xh, *xl, *wdh, *wdl, *wuh, *wul, *wkvuh, *wkvul, *dwn, *dwnh, *dwnl, *qu, *kvf;
    cudaGetSymbolAddress((void**)&xh,    g_xh);
    cudaGetSymbolAddress((void**)&xl,    g_xl);
    cudaGetSymbolAddress((void**)&wdh,   g_wdh);
    cudaGetSymbolAddress((void**)&wdl,   g_wdl);
    cudaGetSymbolAddress((void**)&wuh,   g_wuh);
    cudaGetSymbolAddress((void**)&wul,   g_wul);
    cudaGetSymbolAddress((void**)&wkvuh, g_wkvuh);
    cudaGetSymbolAddress((void**)&wkvul, g_wkvul);
    cudaGetSymbolAddress((void**)&dwn,   g_down);
    cudaGetSymbolAddress((void**)&dwnh,  g_dwnh);
    cudaGetSymbolAddress((void**)&dwnl,  g_dwnl);
    cudaGetSymbolAddress((void**)&qu,    g_qu);
    cudaGetSymbolAddress((void**)&kvf,   g_kv);

    bf16 *q, *k, *v, *vT, *logits, *probs, *attn_bf, *wo_h, *wo_l;
    cudaGetSymbolAddress((void**)&q, g_q);
    cudaGetSymbolAddress((void**)&k, g_k);
    cudaGetSymbolAddress((void**)&v, g_v);
    cudaGetSymbolAddress((void**)&vT, g_vT);
    cudaGetSymbolAddress((void**)&logits, g_logits);
    cudaGetSymbolAddress((void**)&probs, g_probs);
    cudaGetSymbolAddress((void**)&attn_bf, g_attn_bf);
    cudaGetSymbolAddress((void**)&wo_h, g_wo_h);
    cudaGetSymbolAddress((void**)&wo_l, g_wo_l);

    const int TF32_SMEM = 2 * 4 * PSF * 4;   // 81920 B
    cudaFuncSetAttribute(tf32_gemm, cudaFuncAttributeMaxDynamicSharedMemorySize, TF32_SMEM);

    dim3 blk(256);
    auto fgrid = [](int M, int N) {
        return dim3((N + FBN - 1) / FBN, (M + FBM - 1) / FBM, 1);
    };
    auto bgrid = [](int M, int N, int batch) {
        return dim3((N + TBN - 1) / TBN, (M + TBM - 1) / TBM, batch);
    };
    auto split = [&](const float* src, float* hi, float* lo, long n) {
        split_tf32_pl<<<592, 256>>>(src, hi, lo, n);
    };

    // 0) planar tf32 splits (weights concat directly into split buffers) + wo bf16 split
    split(x, xh, xl, (long)S_*E_);
    split(wq_down,  wdh,                 wdl,                 (long)QR_*E_);
    split(wkv_down, wdh + (long)QR_*E_,  wdl + (long)QR_*E_,  (long)KVR_*E_);
    split(wk_rope,  wdh + (long)(QR_+KVR_)*E_, wdl + (long)(QR_+KVR_)*E_, (long)DR_*E_);
    split(wq_up,    wuh,                 wul,                 (long)H_*DV_*QR_);
    split(wq_rope,  wuh + (long)H_*DV_*QR_, wul + (long)H_*DV_*QR_, (long)H_*DR_*QR_);
    split(wkv_up,   wkvuh, wkvul, (long)H_*2*DV_*KVR_);
    split_bf_k<<<592, 256>>>(wo, wo_h, wo_l, (long)E_*H_*DV_);

    // 1) fused down projection: [cq|ckv|kr] = x @ wd^T   (N=1088)
    tf32_gemm<<<fgrid(S_, NDWN), blk, TF32_SMEM>>>(
        xh, xl, wdh, wdl, dwn, S_, NDWN, E_, E_, E_, NDWN);

    // 1b) split latents (whole dwn; kr cols split too but unused — harmless)
    split(dwn, dwnh, dwnl, (long)S_*NDWN);

    // 2) fused q up projection: [qc|qr] = cq @ wu^T
    tf32_gemm<<<fgrid(S_, NQU), blk, TF32_SMEM>>>(
        dwnh, dwnl, wuh, wul, qu, S_, NQU, QR_, NDWN, QR_, NQU);
    // kv up: ckv @ wkv_up^T
    tf32_gemm<<<fgrid(S_, H_*2*DV_), blk, TF32_SMEM>>>(
        dwnh + QR_, dwnl + QR_, wkvuh, wkvul, kvf, S_, H_*2*DV_, KVR_,
        NDWN, KVR_, H_*2*DV_);

    // 3) pack + rope -> head-major bf16 q/k/v ; transpose v
    pack_k<<<S_, 256>>>(qu, kvf, dwn, q, k, v);
    {
        dim3 tg(S_/32, DV_/32, H_);
        dim3 tb(32, 8);
        transpose_v<<<tg, tb>>>(v, vT);
    }

    // 4) logits[h] = bf16( q[h] @ k[h]^T )
    bf16_gemm<bf16><<<bgrid(S_, S_, H_), blk>>>(
        q, q, k, k, logits, 1, S_, S_, DQK_, DQK_, DQK_, S_,
        (long)S_*DQK_, (long)S_*DQK_, (long)S_*S_);

    // 5) softmax
    {
        dim3 g(S_, H_);
        softmax_k<<<g, 256>>>(logits, probs, 1.0f / sqrtf((float)(DV_ + DR_)));
    }

    // 6) attn[h] = bf16( probs[h] @ v[h] ), stored bf16 interleaved [s][h*DV]
    bf16_gemm<bf16><<<bgrid(S_, DV_, H_), blk>>>(
        probs, probs, vT, vT, attn_bf, 1, S_, DV_, S_, S_, S_, (long)H_*DV_,
        (long)S_*S_, (long)DV_*S_, DV_);

    // 7) out = attn(bf16-exact) @ wo^T : 2-pass bf16 (wo = hi + lo)
    bf16_gemm<float><<<bgrid(S_, E_, 1), blk>>>(
        attn_bf, attn_bf, wo_h, wo_l, out, 2, S_, E_, H_*DV_,
        H_*DV_, H_*DV_, E_, 0, 0, 0);
}

// round 9
// speedup vs baseline: 1.0467x; 1.0467x over previous
#include <cuda_runtime.h>
#include <cuda_bf16.h>
#include <math.h>
#include <stdint.h>

#define S_  2048
#define E_  2048
#define H_  16
#define QR_ 512
#define KVR_ 512
#define DR_ 64
#define DV_ 128
#define DQK_ 192   // DV + DR
#define NDWN 1088  // QR + KVR + DR
#define NQU  3072  // H*DV + H*DR

typedef __nv_bfloat16 bf16;

// ---------------- scratch (device globals) ----------------
__device__ float g_wd [NDWN * E_];          // concat [wq_down; wkv_down; wk_rope]
__device__ float g_wu [NQU * QR_];          // concat [wq_up; wq_rope]
__device__ float g_down[S_ * NDWN];         // [cq | ckv | kr] per row
__device__ float g_qu [S_ * NQU];           // [qc | qr] per row
__device__ float g_kv [S_ * (H_*2*DV_)];
__device__ bf16 g_wo_h[E_*H_*DV_], g_wo_l[E_*H_*DV_];
__device__ bf16 g_q[(size_t)H_ * S_ * DQK_];
__device__ bf16 g_k[(size_t)H_ * S_ * DQK_];
__device__ bf16 g_v[(size_t)H_ * S_ * DV_];
__device__ bf16 g_vT[(size_t)H_ * DV_ * S_];
__device__ bf16 g_logits[(size_t)H_ * S_ * S_];
__device__ bf16 g_probs [(size_t)H_ * S_ * S_];
__device__ bf16 g_attn_bf[(size_t)S_ * H_ * DV_];

// ---------------- helpers ----------------
__device__ __forceinline__ uint32_t f2tf32(float x) {
    uint32_t r;
    asm("cvt.rna.tf32.f32 %0, %1;" : "=r"(r) : "f"(x));
    return r;
}

#define MMA_TF32(c, a, b) \
    asm volatile( \
        "mma.sync.aligned.m16n8k8.row.col.f32.tf32.tf32.f32 " \
        "{%0,%1,%2,%3}, {%4,%5,%6,%7}, {%8,%9}, {%0,%1,%2,%3};" \
        : "+f"((c)[0]), "+f"((c)[1]), "+f"((c)[2]), "+f"((c)[3]) \
        : "r"((a)[0]), "r"((a)[1]), "r"((a)[2]), "r"((a)[3]), \
          "r"((b)[0]), "r"((b)[1]))

#define MMA_BF16(c, a, b) \
    asm volatile( \
        "mma.sync.aligned.m16n8k16.row.col.f32.bf16.bf16.f32 " \
        "{%0,%1,%2,%3}, {%4,%5,%6,%7}, {%8,%9}, {%0,%1,%2,%3};" \
        : "+f"((c)[0]), "+f"((c)[1]), "+f"((c)[2]), "+f"((c)[3]) \
        : "r"((a)[0]), "r"((a)[1]), "r"((a)[2]), "r"((a)[3]), \
          "r"((b)[0]), "r"((b)[1]))

#define CP16(dst, src, nbytes) \
    asm volatile("cp.async.cg.shared.global [%0], [%1], 16, %2;" \
                 :: "r"(dst), "l"(src), "r"(nbytes))
#define CP_COMMIT()  asm volatile("cp.async.commit_group;")
#define CP_WAIT0()   asm volatile("cp.async.wait_group 0;")

__global__ void split_bf_k(const float* __restrict__ src, bf16* __restrict__ hi,
                           bf16* __restrict__ lo, long n)
{
    long i = (long)blockIdx.x * blockDim.x + threadIdx.x;
    long stride = (long)gridDim.x * blockDim.x;
    for (; i < n; i += stride) {
        float v = src[i];
        bf16 h = __float2bfloat16(v);
        hi[i] = h;
        lo[i] = __float2bfloat16(v - __bfloat162float(h));
    }
}

// ============================================================================
// 3xTF32 GEMM (R7 proven version), templated on BMv (128 or 64) for wave fill.
// Per-output math identical across tile shapes -> bit-identical results.
// ============================================================================
#define FBN 128
#define FBK 16
#define FPAD 20

template <int BMv>
__global__ __launch_bounds__(256)
void tf32_gemm(const float* __restrict__ A, const float* __restrict__ B,
               float* __restrict__ C, int M, int N, int K,
               long lda, long ldb, long ldc)
{
    constexpr int MT = 2;                    // 2 * 16 rows per warp
    constexpr int NT = (BMv == 128) ? 8 : 4; // nt * 8 cols per warp
    constexpr int ACH = BMv * 4 / 256;       // float4 A-chunks per thread

    __shared__ float sA[2][BMv * FPAD];
    __shared__ float sB[2][FBN * FPAD];

    const int m0 = blockIdx.y * BMv;
    const int n0 = blockIdx.x * FBN;
    const int tid = threadIdx.x;
    const int warp = tid >> 5;
    const int lane = tid & 31;
    const int gid = lane >> 2;
    const int tig = lane & 3;
    const int wm = (BMv == 128) ? (warp >> 1) * 32 : (warp & 1) * 32;
    const int wn = (BMv == 128) ? (warp & 1) * 64  : (warp >> 1) * 32;

    const float* aSrc[ACH];
    uint32_t aOff[ACH];
    const float* bSrc[2];
    uint32_t bOff[2];
    int bPred[2];
    const uint32_t saBase = (uint32_t)__cvta_generic_to_shared(sA);
    const uint32_t sbBase = (uint32_t)__cvta_generic_to_shared(sB);
#pragma unroll
    for (int it = 0; it < ACH; it++) {
        int idx = tid + it * 256;
        int row = idx >> 2, ch = idx & 3;
        aSrc[it] = A + (long)(m0 + row) * lda + ch * 4;
        aOff[it] = (uint32_t)(row * FPAD + ch * 4) * 4u;
    }
#pragma unroll
    for (int it = 0; it < 2; it++) {
        int idx = tid + it * 256;
        int row = idx >> 2, ch = idx & 3;
        int nrow = n0 + row;
        bPred[it] = (nrow < N) ? 16 : 0;
        if (nrow >= N) nrow = N - 1;
        bSrc[it] = B + (long)nrow * ldb + ch * 4;
        bOff[it] = (uint32_t)(row * FPAD + ch * 4) * 4u;
    }
    const uint32_t ABUF = BMv * FPAD * 4u;
    const uint32_t BBUF = FBN * FPAD * 4u;

    float acc[MT][NT][4];
#pragma unroll
    for (int mt = 0; mt < MT; mt++)
#pragma unroll
        for (int nt = 0; nt < NT; nt++)
#pragma unroll
            for (int r = 0; r < 4; r++) acc[mt][nt][r] = 0.f;

    const int NTILES = K / FBK;

#pragma unroll
    for (int it = 0; it < ACH; it++) CP16(saBase + aOff[it], aSrc[it], 16);
#pragma unroll
    for (int it = 0; it < 2; it++)   CP16(sbBase + bOff[it], bSrc[it], bPred[it]);
    CP_COMMIT();

    for (int t = 0; t < NTILES; t++) {
        const int cur = t & 1;
        CP_WAIT0();
        __syncthreads();

        if (t + 1 < NTILES) {
            const long kk = (long)(t + 1) * FBK;
#pragma unroll
            for (int it = 0; it < ACH; it++)
                CP16(saBase + (cur ^ 1) * ABUF + aOff[it], aSrc[it] + kk, 16);
#pragma unroll
            for (int it = 0; it < 2; it++)
                CP16(sbBase + (cur ^ 1) * BBUF + bOff[it], bSrc[it] + kk, bPred[it]);
            CP_COMMIT();
        }

        const float* cA = sA[cur];
        const float* cB = sB[cur];

        uint32_t ah[2][MT][4], al[2][MT][4];
#pragma unroll
        for (int ks = 0; ks < 2; ks++)
#pragma unroll
            for (int mt = 0; mt < MT; mt++)
#pragma unroll
                for (int r = 0; r < 4; r++) {
                    int row = wm + mt * 16 + gid + (r & 1) * 8;
                    int col = ks * 8 + tig + (r >> 1) * 4;
                    float v = cA[row * FPAD + col];
                    uint32_t h = f2tf32(v);
                    ah[ks][mt][r] = h;
                    al[ks][mt][r] = f2tf32(v - __uint_as_float(h));
                }

#pragma unroll
        for (int nt = 0; nt < NT; nt++) {
            uint32_t bh[2][2], bl[2][2];
#pragma unroll
            for (int ks = 0; ks < 2; ks++)
#pragma unroll
                for (int r = 0; r < 2; r++) {
                    int n = wn + nt * 8 + gid;
                    int kq = ks * 8 + tig + r * 4;
                    float v = cB[n * FPAD + kq];
                    uint32_t h = f2tf32(v);
                    bh[ks][r] = h;
                    bl[ks][r] = f2tf32(v - __uint_as_float(h));
                }
#pragma unroll
            for (int mt = 0; mt < MT; mt++) {
                float f[4] = {0.f, 0.f, 0.f, 0.f};
#pragma unroll
                for (int ks = 0; ks < 2; ks++) {
                    MMA_TF32(f, ah[ks][mt], bh[ks]);
                    MMA_TF32(f, ah[ks][mt], bl[ks]);
                    MMA_TF32(f, al[ks][mt], bh[ks]);
                }
                float* c = acc[mt][nt];
                c[0] += f[0]; c[1] += f[1]; c[2] += f[2]; c[3] += f[3];
            }
        }
    }

#pragma unroll
    for (int mt = 0; mt < MT; mt++) {
        int row0 = m0 + wm + mt * 16 + gid;
#pragma unroll
        for (int nt = 0; nt < NT; nt++) {
            int n = n0 + wn + nt * 8 + tig * 2;
            if (n >= N) continue;
            float* c = acc[mt][nt];
            C[(long)row0 * ldc + n]         = c[0];
            C[(long)row0 * ldc + n + 1]     = c[1];
            C[(long)(row0+8) * ldc + n]     = c[2];
            C[(long)(row0+8) * ldc + n + 1] = c[3];
        }
    }
}

// ============================================================================
// bf16 tensor-core GEMM, chunked-IEEE accumulation, cp.async double-buffered,
// multi-pass (npass operand pairs accumulated in fp32). (unchanged from R7)
// ============================================================================
#define TBM 128
#define TBN 128
#define TBK 32
#define PADK 40

template <typename TC>
__global__ __launch_bounds__(256)
void bf16_gemm(const bf16* __restrict__ A0, const bf16* __restrict__ A1,
               const bf16* __restrict__ B0, const bf16* __restrict__ B1,
               TC* __restrict__ C, int npass, int M, int N, int K,
               long lda, long ldb, long ldc, long Abat, long Bbat, long Cbat)
{
    __shared__ bf16 sA[2][TBM * PADK];
    __shared__ bf16 sB[2][TBN * PADK];

    const long zo = blockIdx.z;
    C += zo * Cbat;

    const int m0 = blockIdx.y * TBM;
    const int n0 = blockIdx.x * TBN;
    const int tid = threadIdx.x;
    const int warp = tid >> 5;
    const int lane = tid & 31;
    const int gid = lane >> 2;
    const int tig = lane & 3;
    const int wm = (warp >> 1) * 32;
    const int wn = (warp & 1) * 64;

    const uint32_t saBase = (uint32_t)__cvta_generic_to_shared(sA);
    const uint32_t sbBase = (uint32_t)__cvta_generic_to_shared(sB);
    const uint32_t ABUF = TBM * PADK * 2u;

    float acc[2][8][4];
#pragma unroll
    for (int mt = 0; mt < 2; mt++)
#pragma unroll
        for (int nt = 0; nt < 8; nt++)
#pragma unroll
            for (int r = 0; r < 4; r++) acc[mt][nt][r] = 0.f;

    const int NT = K / TBK;

    for (int p = 0; p < npass; p++) {
        const bf16* A = (p ? A1 : A0) + zo * Abat;
        const bf16* B = (p ? B1 : B0) + zo * Bbat;

        const bf16* aSrc[2];
        const bf16* bSrc[2];
        uint32_t sOff[2];
        int bPred[2];
#pragma unroll
        for (int it = 0; it < 2; it++) {
            int idx = tid + it * 256;
            int row = idx >> 2, ch = idx & 3;
            aSrc[it] = A + (long)(m0 + row) * lda + ch * 8;
            int nrow = n0 + row;
            bPred[it] = (nrow < N) ? 16 : 0;
            if (nrow >= N) nrow = N - 1;
            bSrc[it] = B + (long)nrow * ldb + ch * 8;
            sOff[it] = (uint32_t)(row * PADK + ch * 8) * 2u;
        }

        if (p) __syncthreads();

#pragma unroll
        for (int it = 0; it < 2; it++) {
            CP16(saBase + sOff[it], aSrc[it], 16);
            CP16(sbBase + sOff[it], bSrc[it], bPred[it]);
        }
        CP_COMMIT();

        for (int t = 0; t < NT; t++) {
            const int cur = t & 1;
            CP_WAIT0();
            __syncthreads();

            if (t + 1 < NT) {
                const long kk = (long)(t + 1) * TBK;
                const uint32_t bo = (cur ^ 1) * ABUF;
#pragma unroll
                for (int it = 0; it < 2; it++) {
                    CP16(saBase + bo + sOff[it], aSrc[it] + kk, 16);
                    CP16(sbBase + bo + sOff[it], bSrc[it] + kk, bPred[it]);
                }
                CP_COMMIT();
            }

            const bf16* cA = sA[cur];
            const bf16* cB = sB[cur];

            uint32_t a[2][2][4];
#pragma unroll
            for (int ks = 0; ks < 2; ks++)
#pragma unroll
                for (int mt = 0; mt < 2; mt++)
#pragma unroll
                    for (int r = 0; r < 4; r++) {
                        int row = wm + mt * 16 + gid + (r & 1) * 8;
                        int col = ks * 16 + tig * 2 + (r >> 1) * 8;
                        a[ks][mt][r] = *(const uint32_t*)&cA[row * PADK + col];
                    }

#pragma unroll
            for (int nt = 0; nt < 8; nt++) {
                uint32_t b[2][2];
#pragma unroll
                for (int ks = 0; ks < 2; ks++)
#pragma unroll
                    for (int r = 0; r < 2; r++) {
                        int n  = wn + nt * 8 + gid;
                        int kq = ks * 16 + tig * 2 + r * 8;
                        b[ks][r] = *(const uint32_t*)&cB[n * PADK + kq];
                    }
#pragma unroll
                for (int mt = 0; mt < 2; mt++) {
                    float f[4] = {0.f, 0.f, 0.f, 0.f};
                    MMA_BF16(f, a[0][mt], b[0]);
                    MMA_BF16(f, a[1][mt], b[1]);
                    float* c = acc[mt][nt];
                    c[0] += f[0]; c[1] += f[1]; c[2] += f[2]; c[3] += f[3];
                }
            }
        }
    }

#pragma unroll
    for (int mt = 0; mt < 2; mt++) {
        int row0 = m0 + wm + mt * 16 + gid;
#pragma unroll
        for (int nt = 0; nt < 8; nt++) {
            int n = n0 + wn + nt * 8 + tig * 2;
            if (n >= N) continue;
            float* c = acc[mt][nt];
            if (sizeof(TC) == 4) {
                float* Cf = (float*)C;
                Cf[(long)row0 * ldc + n]         = c[0];
                Cf[(long)row0 * ldc + n + 1]     = c[1];
                Cf[(long)(row0+8) * ldc + n]     = c[2];
                Cf[(long)(row0+8) * ldc + n + 1] = c[3];
            } else {
                bf16* Cb = (bf16*)C;
                *(__nv_bfloat162*)&Cb[(long)row0 * ldc + n] =
                    __nv_bfloat162(__float2bfloat16(c[0]), __float2bfloat16(c[1]));
                *(__nv_bfloat162*)&Cb[(long)(row0+8) * ldc + n] =
                    __nv_bfloat162(__float2bfloat16(c[2]), __float2bfloat16(c[3]));
            }
        }
    }
}

// ---------------- pack q/k/v (bf16, head-major) + RoPE ----------------
__global__ void pack_k(const float* __restrict__ qu, const float* __restrict__ kvf,
                       const float* __restrict__ dwn,
                       bf16* __restrict__ q, bf16* __restrict__ k, bf16* __restrict__ v)
{
    const int s = blockIdx.x;
    const int tid = threadIdx.x;  // 256

    __shared__ float ssin[32], scos[32];
    if (tid < 32) {
        double invf_d = pow(10000.0, -((double)(2 * tid)) / 64.0);
        float invf = (float)invf_d;
        float ang = (float)s * invf;
        double a = (double)ang;
        ssin[tid] = (float)sin(a);
        scos[tid] = (float)cos(a);
    }
    __syncthreads();

    for (int idx = tid; idx < H_ * DV_; idx += 256) {
        int h = idx >> 7, d = idx & 127;
        q[((long)h * S_ + s) * DQK_ + d] = __float2bfloat16(qu[(long)s * NQU + idx]);
        k[((long)h * S_ + s) * DQK_ + d] = __float2bfloat16(kvf[(long)s * (H_*2*DV_) + idx]);
        v[((long)h * S_ + s) * DV_ + d]  = __float2bfloat16(kvf[(long)s * (H_*2*DV_) + H_*DV_ + idx]);
    }

    for (int idx = tid; idx < H_ * 32; idx += 256) {
        int h = idx >> 5, j = idx & 31;
        float x1 = qu[(long)s * NQU + 2048 + h * DR_ + j];
        float x2 = qu[(long)s * NQU + 2048 + h * DR_ + 32 + j];
        float sn = ssin[j], cs = scos[j];
        q[((long)h * S_ + s) * DQK_ + DV_ + j]      = __float2bfloat16(x1 * cs - x2 * sn);
        q[((long)h * S_ + s) * DQK_ + DV_ + 32 + j] = __float2bfloat16(x2 * cs + x1 * sn);
    }

    if (tid < 32) {
        int j = tid;
        float x1 = dwn[(long)s * NDWN + 1024 + j];
        float x2 = dwn[(long)s * NDWN + 1024 + 32 + j];
        float sn = ssin[j], cs = scos[j];
        float r1 = x1 * cs - x2 * sn;
        float r2 = x2 * cs + x1 * sn;
#pragma unroll
        for (int h = 0; h < H_; h++) {
            k[((long)h * S_ + s) * DQK_ + DV_ + j]      = __float2bfloat16(r1);
            k[((long)h * S_ + s) * DQK_ + DV_ + 32 + j] = __float2bfloat16(r2);
        }
    }
}

// ---------------- transpose v [h][s][d] -> vT [h][d][s] ----------------
__global__ void transpose_v(const bf16* __restrict__ v, bf16* __restrict__ vT)
{
    __shared__ bf16 t[32][33];
    const int h = blockIdx.z;
    const int s0 = blockIdx.x * 32;
    const int d0 = blockIdx.y * 32;
    const int tx = threadIdx.x, ty = threadIdx.y;  // (32, 8)
#pragma unroll
    for (int j = 0; j < 32; j += 8)
        t[ty + j][tx] = v[((long)h * S_ + s0 + ty + j) * DV_ + d0 + tx];
    __syncthreads();
#pragma unroll
    for (int j = 0; j < 32; j += 8)
        vT[((long)h * DV_ + d0 + ty + j) * S_ + s0 + tx] = t[tx][ty + j];
}

// ---------------- softmax over bf16 logits -> bf16 probs ----------------
__global__ void softmax_k(const bf16* __restrict__ L, bf16* __restrict__ P, float scale)
{
    const int s = blockIdx.x;
    const int h = blockIdx.y;
    const bf16* row = L + ((long)h * S_ + s) * S_;
    bf16* prow = P + ((long)h * S_ + s) * S_;
    const int tid = threadIdx.x;

    float v[8];
    float mx = -1e30f;
#pragma unroll
    for (int i = 0; i < 8; i++) {
        v[i] = __bfloat162float(row[tid + i * 256]) * scale;
        mx = fmaxf(mx, v[i]);
    }
    __shared__ float red[256];
    red[tid] = mx;
    __syncthreads();
    for (int st = 128; st > 0; st >>= 1) {
        if (tid < st) red[tid] = fmaxf(red[tid], red[tid + st]);
        __syncthreads();
    }
    mx = red[0];
    __syncthreads();

    float sum = 0.f;
#pragma unroll
    for (int i = 0; i < 8; i++) {
        v[i] = expf(v[i] - mx);
        sum += v[i];
    }
    red[tid] = sum;
    __syncthreads();
    for (int st = 128; st > 0; st >>= 1) {
        if (tid < st) red[tid] += red[tid + st];
        __syncthreads();
    }
    float tot = red[0];
#pragma unroll
    for (int i = 0; i < 8; i++)
        prow[tid + i * 256] = __float2bfloat16(v[i] / tot);
}

// ---------------- orchestration ----------------
extern "C" void kernel_launch(void* const* d_in, const int* in_sizes, int n_in,
                              void* d_out, int out_size)
{
    (void)in_sizes; (void)n_in; (void)out_size;
    const float* x       = (const float*)d_in[0];
    const float* wq_down = (const float*)d_in[1];
    const float* wq_up   = (const float*)d_in[2];
    const float* wq_rope = (const float*)d_in[3];
    const float* wkv_down= (const float*)d_in[4];
    const float* wkv_up  = (const float*)d_in[5];
    const float* wk_rope = (const float*)d_in[6];
    const float* wo      = (const float*)d_in[7];
    float* out = (float*)d_out;

    float *wd, *wu, *dwn, *qu, *kvf;
    cudaGetSymbolAddress((void**)&wd,  g_wd);
    cudaGetSymbolAddress((void**)&wu,  g_wu);
    cudaGetSymbolAddress((void**)&dwn, g_down);
    cudaGetSymbolAddress((void**)&qu,  g_qu);
    cudaGetSymbolAddress((void**)&kvf, g_kv);

    bf16 *q, *k, *v, *vT, *logits, *probs, *attn_bf, *wo_h, *wo_l;
    cudaGetSymbolAddress((void**)&q, g_q);
    cudaGetSymbolAddress((void**)&k, g_k);
    cudaGetSymbolAddress((void**)&v, g_v);
    cudaGetSymbolAddress((void**)&vT, g_vT);
    cudaGetSymbolAddress((void**)&logits, g_logits);
    cudaGetSymbolAddress((void**)&probs, g_probs);
    cudaGetSymbolAddress((void**)&attn_bf, g_attn_bf);
    cudaGetSymbolAddress((void**)&wo_h, g_wo_h);
    cudaGetSymbolAddress((void**)&wo_l, g_wo_l);

    dim3 blk(256);
    auto bgrid = [](int M, int N, int batch) {
        return dim3((N + TBN - 1) / TBN, (M + TBM - 1) / TBM, batch);
    };

    // 0) concat weights (D2D, graph-capturable) + wo bf16 split
    cudaMemcpyAsync(wd,                 wq_down,  (size_t)QR_ * E_ * 4, cudaMemcpyDeviceToDevice);
    cudaMemcpyAsync(wd + (size_t)QR_*E_, wkv_down, (size_t)KVR_ * E_ * 4, cudaMemcpyDeviceToDevice);
    cudaMemcpyAsync(wd + (size_t)(QR_+KVR_)*E_, wk_rope, (size_t)DR_ * E_ * 4, cudaMemcpyDeviceToDevice);
    cudaMemcpyAsync(wu,                  wq_up,   (size_t)H_*DV_ * QR_ * 4, cudaMemcpyDeviceToDevice);
    cudaMemcpyAsync(wu + (size_t)H_*DV_*QR_, wq_rope, (size_t)H_*DR_ * QR_ * 4, cudaMemcpyDeviceToDevice);
    split_bf_k<<<592, 256>>>(wo, wo_h, wo_l, (long)E_*H_*DV_);

    // 1) fused down projection: [cq|ckv|kr] = x @ wd^T   (N=1088)
    //    BM=64 variant: grid 9 x 32 = 288 CTAs ~ 0.97 waves (vs 144 = 0.49)
    tf32_gemm<64><<<dim3((NDWN + FBN - 1) / FBN, S_ / 64, 1), blk>>>(
        x, wd, dwn, S_, NDWN, E_, E_, E_, NDWN);

    // 2) fused q up projection: [qc|qr] = cq @ wu^T  (BM=64: 24 x 32 = 768 CTAs)
    tf32_gemm<64><<<dim3(NQU / FBN, S_ / 64, 1), blk>>>(
        dwn, wu, qu, S_, NQU, QR_, NDWN, QR_, NQU);
    // kv up: ckv @ wkv_up^T  (BM=128: 32 x 16 = 512 CTAs, 1.73 waves - keep)
    tf32_gemm<128><<<dim3((H_*2*DV_) / FBN, S_ / 128, 1), blk>>>(
        dwn + QR_, wkv_up, kvf, S_, H_*2*DV_, KVR_, NDWN, KVR_, H_*2*DV_);

    // 3) pack + rope -> head-major bf16 q/k/v ; transpose v
    pack_k<<<S_, 256>>>(qu, kvf, dwn, q, k, v);
    {
        dim3 tg(S_/32, DV_/32, H_);
        dim3 tb(32, 8);
        transpose_v<<<tg, tb>>>(v, vT);
    }

    // 4) logits[h] = bf16( q[h] @ k[h]^T )
    bf16_gemm<bf16><<<bgrid(S_, S_, H_), blk>>>(
        q, q, k, k, logits, 1, S_, S_, DQK_, DQK_, DQK_, S_,
        (long)S_*DQK_, (long)S_*DQK_, (long)S_*S_);

    // 5) softmax
    {
        dim3 g(S_, H_);
        softmax_k<<<g, 256>>>(logits, probs, 1.0f / sqrtf((float)(DV_ + DR_)));
    }

    // 6) attn[h] = bf16( probs[h] @ v[h] ), stored bf16 interleaved [s][h*DV]
    bf16_gemm<bf16><<<bgrid(S_, DV_, H_), blk>>>(
        probs, probs, vT, vT, attn_bf, 1, S_, DV_, S_, S_, S_, (long)H_*DV_,
        (long)S_*S_, (long)DV_*S_, DV_);

    // 7) out = attn(bf16-exact) @ wo^T : 2-pass bf16 (wo = hi + lo)
    bf16_gemm<float><<<bgrid(S_, E_, 1), blk>>>(
        attn_bf, attn_bf, wo_h, wo_l, out, 2, S_, E_, H_*DV_,
        H_*DV_, H_*DV_, E_, 0, 0, 0);
}